// round 2
// baseline (speedup 1.0000x reference)
#include <cuda_runtime.h>
#include <cuda_bf16.h>
#include <cstdint>

#define DIM 128
#define WT_STRIDE 132   // padded row stride for transposed W (bank-conflict-free)
#define MAXV 100000

// Scratch (device globals; no allocation allowed)
__device__ float g_h[MAXV * DIM];      // dinv[v] * (emb @ W)[v]
__device__ float g_nodes[MAXV * DIM];  // aggregated output (pre-bias)
__device__ float g_deg[MAXV];
__device__ float g_dinv[MAXV];
__device__ float g_wt[DIM * WT_STRIDE]; // W transposed: g_wt[c*132 + k] = W[k][c]

// ---------------------------------------------------------------------------
// packed f32x2 helpers
// ---------------------------------------------------------------------------
__device__ __forceinline__ unsigned long long ffma2(unsigned long long a,
                                                    unsigned long long b,
                                                    unsigned long long c) {
    unsigned long long d;
    asm("fma.rn.f32x2 %0, %1, %2, %3;" : "=l"(d) : "l"(a), "l"(b), "l"(c));
    return d;
}
__device__ __forceinline__ float hadd2(unsigned long long p) {
    float lo, hi;
    asm("mov.b64 {%0, %1}, %2;" : "=f"(lo), "=f"(hi) : "l"(p));
    return lo + hi;
}

// ---------------------------------------------------------------------------
// degree pipeline
// ---------------------------------------------------------------------------
__global__ void k_init_deg(int V) {
    int v = blockIdx.x * blockDim.x + threadIdx.x;
    if (v < V) g_deg[v] = 1.0f;  // self-loop
}

__global__ void k_deg(const int* __restrict__ edge, int E) {
    int e = blockIdx.x * blockDim.x + threadIdx.x;
    if (e < E) atomicAdd(&g_deg[edge[E + e]], 1.0f);  // dst = edge_index[1]
}

__global__ void k_dinv(int V) {
    int v = blockIdx.x * blockDim.x + threadIdx.x;
    if (v < V) g_dinv[v] = rsqrtf(g_deg[v]);
}

// ---------------------------------------------------------------------------
// transpose W into padded g_wt (one-time, 64KB)
// ---------------------------------------------------------------------------
__global__ void k_transpose_w(const float* __restrict__ W) {
    int gid = blockIdx.x * blockDim.x + threadIdx.x;  // k*128 + c
    if (gid < DIM * DIM) {
        int k = gid >> 7;
        int c = gid & 127;
        g_wt[c * WT_STRIDE + k] = W[gid];
    }
}

// ---------------------------------------------------------------------------
// GEMM: g_h = dinv * (X @ W), g_nodes = dinv^2 * (X @ W)   (selfloop fused)
// k-packed f32x2: acc pair accumulates (even-k, odd-k) partial sums.
// Block = 256 threads: 8 row-groups x 32 col-groups, thread tile 4x4.
// Block tile: 32 rows x 128 cols. Shared: wT (67.6KB, padded) + X tile (16KB).
// ---------------------------------------------------------------------------
__global__ void __launch_bounds__(256) k_gemm(const float* __restrict__ X, int V) {
    extern __shared__ float sh[];
    float* w_sh = sh;                         // [128][132]
    float* x_sh = sh + DIM * WT_STRIDE;       // [32][128]

    const int tid  = threadIdx.x;
    const int row0 = blockIdx.x * 32;

    // load transposed W: 128*33 float4 = 4224; 17 per thread (guarded)
    {
        const float4* src = reinterpret_cast<const float4*>(g_wt);
        float4* dst = reinterpret_cast<float4*>(w_sh);
        const int total = DIM * (WT_STRIDE / 4);  // 4224
#pragma unroll
        for (int i = 0; i < 17; i++) {
            int idx = tid + i * 256;
            if (idx < total) dst[idx] = src[idx];
        }
    }
    // load X tile: 32 rows x 32 float4 = 1024; 4 per thread (row-guarded)
    {
        const float4* X4 = reinterpret_cast<const float4*>(X) + (size_t)row0 * 32;
        float4* x4 = reinterpret_cast<float4*>(x_sh);
#pragma unroll
        for (int i = 0; i < 4; i++) {
            int idx = tid + i * 256;
            int r = idx >> 5;
            float4 v = make_float4(0.f, 0.f, 0.f, 0.f);
            if (row0 + r < V) v = X4[idx];
            x4[idx] = v;
        }
    }
    __syncthreads();

    const int cg = tid & 31;   // cols cg*4 .. +3
    const int rg = tid >> 5;   // rows rg*4 .. +3

    unsigned long long acc[4][4];
#pragma unroll
    for (int r = 0; r < 4; r++)
#pragma unroll
        for (int c = 0; c < 4; c++) acc[r][c] = 0ull;

    const float* xb = x_sh + (rg * 4) * DIM;
    const float* wb = w_sh + (cg * 4) * WT_STRIDE;

#pragma unroll 8
    for (int kk = 0; kk < DIM; kk += 4) {
        ulonglong2 xv[4], wv[4];
#pragma unroll
        for (int r = 0; r < 4; r++)
            xv[r] = *reinterpret_cast<const ulonglong2*>(xb + r * DIM + kk);
#pragma unroll
        for (int c = 0; c < 4; c++)
            wv[c] = *reinterpret_cast<const ulonglong2*>(wb + c * WT_STRIDE + kk);
#pragma unroll
        for (int r = 0; r < 4; r++)
#pragma unroll
            for (int c = 0; c < 4; c++) {
                acc[r][c] = ffma2(xv[r].x, wv[c].x, acc[r][c]);
                acc[r][c] = ffma2(xv[r].y, wv[c].y, acc[r][c]);
            }
    }

#pragma unroll
    for (int r = 0; r < 4; r++) {
        int row = row0 + rg * 4 + r;
        if (row < V) {
            float s  = g_dinv[row];
            float s2 = s * s;
            float4 o;
            o.x = hadd2(acc[r][0]); o.y = hadd2(acc[r][1]);
            o.z = hadd2(acc[r][2]); o.w = hadd2(acc[r][3]);
            float4 hsc = make_float4(o.x * s,  o.y * s,  o.z * s,  o.w * s);
            float4 nsc = make_float4(o.x * s2, o.y * s2, o.z * s2, o.w * s2);
            size_t off = (size_t)row * 32 + cg;
            reinterpret_cast<float4*>(g_h)[off]     = hsc;
            reinterpret_cast<float4*>(g_nodes)[off] = nsc;
        }
    }
}

// ---------------------------------------------------------------------------
// edge aggregation: one warp per edge; g_h already carries dinv[src].
// ---------------------------------------------------------------------------
__global__ void __launch_bounds__(256) k_edge_agg(const int* __restrict__ edge, int E) {
    int warp = (blockIdx.x * blockDim.x + threadIdx.x) >> 5;
    int lane = threadIdx.x & 31;
    if (warp >= E) return;
    int src = __ldg(edge + warp);       // edge_index[0]
    int dst = __ldg(edge + E + warp);   // edge_index[1]
    float norm = __ldg(g_dinv + dst);   // dinv[src] already folded into g_h
    const float4 v = reinterpret_cast<const float4*>(g_h)[(size_t)src * 32 + lane];
    float* p = g_nodes + (size_t)dst * DIM + lane * 4;
    asm volatile("red.global.add.v4.f32 [%0], {%1, %2, %3, %4};"
                 :: "l"(p), "f"(v.x * norm), "f"(v.y * norm),
                    "f"(v.z * norm), "f"(v.w * norm)
                 : "memory");
}

// ---------------------------------------------------------------------------
// scoring: shuffle-free. Block = 4 items x 64 samples; 1 thread = 1 sample.
// scores[b,s] = dot(nodes[item]+bias, nodes[sample]+bias)
// ---------------------------------------------------------------------------
__global__ void __launch_bounds__(256) k_scores(const int* __restrict__ items,
                                                const int* __restrict__ samples,
                                                const float* __restrict__ bias,
                                                float* __restrict__ out,
                                                int B, int S) {
    __shared__ float item_sh[4][DIM];   // item + bias
    __shared__ float bias_sh[DIM];
    const int t  = threadIdx.x;
    const int b0 = blockIdx.x * 4;

    if (t < DIM) bias_sh[t] = __ldg(bias + t);
    __syncthreads();
#pragma unroll
    for (int i = 0; i < 2; i++) {
        int lin = t + i * 256;          // 0..511
        int ii  = lin >> 7;             // item slot 0..3
        int d   = lin & 127;
        int bi  = b0 + ii;
        if (bi < B) {
            int item = __ldg(items + bi);
            item_sh[ii][d] = g_nodes[(size_t)item * DIM + d] + bias_sh[d];
        }
    }
    __syncthreads();

    const int ii = t >> 6;              // item slot
    const int s  = t & 63;              // sample index
    const int bi = b0 + ii;
    if (bi >= B) return;

    const int sidx = __ldg(samples + (size_t)bi * S + s);
    const float4* srow = reinterpret_cast<const float4*>(g_nodes) + (size_t)sidx * 32;
    const float4* irow = reinterpret_cast<const float4*>(item_sh[ii]);
    const float4* brow = reinterpret_cast<const float4*>(bias_sh);

    float4 acc = make_float4(0.f, 0.f, 0.f, 0.f);
#pragma unroll 8
    for (int j = 0; j < 32; j++) {
        float4 sv = srow[j];
        float4 iv = irow[j];
        float4 bv = brow[j];
        acc.x = fmaf(iv.x, sv.x + bv.x, acc.x);
        acc.y = fmaf(iv.y, sv.y + bv.y, acc.y);
        acc.z = fmaf(iv.z, sv.z + bv.z, acc.z);
        acc.w = fmaf(iv.w, sv.w + bv.w, acc.w);
    }
    out[(size_t)bi * S + s] = (acc.x + acc.y) + (acc.z + acc.w);
}

// ---------------------------------------------------------------------------
// launcher
// ---------------------------------------------------------------------------
extern "C" void kernel_launch(void* const* d_in, const int* in_sizes, int n_in,
                              void* d_out, int out_size) {
    const int*   items   = (const int*)d_in[0];
    const int*   samples = (const int*)d_in[1];
    const int*   edge    = (const int*)d_in[2];
    const float* emb     = (const float*)d_in[3];
    const float* W       = (const float*)d_in[4];
    const float* bias    = (const float*)d_in[5];
    float*       out     = (float*)d_out;

    const int B = in_sizes[0];
    const int S = in_sizes[1] / B;
    const int E = in_sizes[2] / 2;
    const int V = in_sizes[3] / DIM;

    // degrees
    k_init_deg<<<(V + 255) / 256, 256>>>(V);
    k_deg<<<(E + 255) / 256, 256>>>(edge, E);
    k_dinv<<<(V + 255) / 256, 256>>>(V);

    // W transpose (tiny) — independent of degree pipeline
    k_transpose_w<<<(DIM * DIM + 255) / 256, 256>>>(W);

    // GEMM + fused self-loop/scaling
    const int gemm_smem = (DIM * WT_STRIDE + 32 * DIM) * (int)sizeof(float); // 83968
    cudaFuncSetAttribute(k_gemm, cudaFuncAttributeMaxDynamicSharedMemorySize, gemm_smem);
    k_gemm<<<(V + 31) / 32, 256, gemm_smem>>>(emb, V);

    // edge scatter-add
    k_edge_agg<<<(E + 7) / 8, 256>>>(edge, E);

    // scoring with folded bias
    k_scores<<<(B + 3) / 4, 256>>>(items, samples, bias, out, B, S);
}

// round 3
// speedup vs baseline: 1.3839x; 1.3839x over previous
#include <cuda_runtime.h>
#include <cuda_bf16.h>
#include <cstdint>

#define DIM 128
#define WT_STRIDE 132   // padded row stride for transposed W
#define MAXV 100000

// Scratch (device globals; no allocation allowed)
__device__ float g_h[MAXV * DIM];      // dinv[v] * (emb @ W)[v]
__device__ float g_nodes[MAXV * DIM];  // aggregated output (pre-bias)
__device__ float g_deg[MAXV];
__device__ float g_dinv[MAXV];
__device__ float g_wt[DIM * WT_STRIDE]; // g_wt[c*132 + k] = W[k][c]

// ---------------------------------------------------------------------------
// packed f32x2 helpers
// ---------------------------------------------------------------------------
__device__ __forceinline__ unsigned long long ffma2(unsigned long long a,
                                                    unsigned long long b,
                                                    unsigned long long c) {
    unsigned long long d;
    asm("fma.rn.f32x2 %0, %1, %2, %3;" : "=l"(d) : "l"(a), "l"(b), "l"(c));
    return d;
}
__device__ __forceinline__ float hadd2(unsigned long long p) {
    float lo, hi;
    asm("mov.b64 {%0, %1}, %2;" : "=f"(lo), "=f"(hi) : "l"(p));
    return lo + hi;
}

// ---------------------------------------------------------------------------
// degree pipeline
// ---------------------------------------------------------------------------
__global__ void k_init_deg(int V) {
    int v = blockIdx.x * blockDim.x + threadIdx.x;
    if (v < V) g_deg[v] = 1.0f;  // self-loop
}

__global__ void k_deg(const int* __restrict__ edge, int E) {
    int e = blockIdx.x * blockDim.x + threadIdx.x;
    if (e < E) atomicAdd(&g_deg[edge[E + e]], 1.0f);  // dst = edge_index[1]
}

__global__ void k_dinv(int V) {
    int v = blockIdx.x * blockDim.x + threadIdx.x;
    if (v < V) g_dinv[v] = rsqrtf(g_deg[v]);
}

// ---------------------------------------------------------------------------
// transpose W into padded g_wt (one-time, 64KB)
// ---------------------------------------------------------------------------
__global__ void k_transpose_w(const float* __restrict__ W) {
    int gid = blockIdx.x * blockDim.x + threadIdx.x;  // k*128 + c
    if (gid < DIM * DIM) {
        int k = gid >> 7;
        int c = gid & 127;
        g_wt[c * WT_STRIDE + k] = W[gid];
    }
}

// ---------------------------------------------------------------------------
// GEMM: g_h = dinv * (X @ W), g_nodes = dinv^2 * (X @ W)   (selfloop fused)
// k-packed f32x2. Block = 128 threads = 4 warps; block tile 32 rows x 128 cols.
// Thread tile: 8 rows (rg*8..+7, warp-uniform -> broadcast LDS) x 4 cols
// (cg + c*32, lane stride 132 words == 4 mod 32 -> conflict-free LDS.128).
// ---------------------------------------------------------------------------
__global__ void __launch_bounds__(128) k_gemm(const float* __restrict__ X, int V) {
    extern __shared__ float sh[];
    float* w_sh = sh;                         // [128][132]
    float* x_sh = sh + DIM * WT_STRIDE;       // [32][128]

    const int tid  = threadIdx.x;
    const int row0 = blockIdx.x * 32;

    // load transposed W: 4224 float4; 33 per thread
    {
        const float4* src = reinterpret_cast<const float4*>(g_wt);
        float4* dst = reinterpret_cast<float4*>(w_sh);
#pragma unroll
        for (int i = 0; i < 33; i++) dst[tid + i * 128] = src[tid + i * 128];
    }
    // load X tile: 32 rows x 32 float4 = 1024; 8 per thread (row-guarded)
    {
        const float4* X4 = reinterpret_cast<const float4*>(X) + (size_t)row0 * 32;
        float4* x4 = reinterpret_cast<float4*>(x_sh);
#pragma unroll
        for (int i = 0; i < 8; i++) {
            int idx = tid + i * 128;
            int r = idx >> 5;
            float4 v = make_float4(0.f, 0.f, 0.f, 0.f);
            if (row0 + r < V) v = X4[idx];
            x4[idx] = v;
        }
    }
    __syncthreads();

    const int cg = tid & 31;   // cols: cg, cg+32, cg+64, cg+96
    const int rg = tid >> 5;   // rows: rg*8 .. rg*8+7

    unsigned long long acc[8][4];
#pragma unroll
    for (int r = 0; r < 8; r++)
#pragma unroll
        for (int c = 0; c < 4; c++) acc[r][c] = 0ull;

    const float* xb = x_sh + (rg * 8) * DIM;
    const float* wb = w_sh + cg * WT_STRIDE;

#pragma unroll 4
    for (int kk = 0; kk < DIM; kk += 4) {
        ulonglong2 wv[4];
#pragma unroll
        for (int c = 0; c < 4; c++)
            wv[c] = *reinterpret_cast<const ulonglong2*>(wb + (c * 32) * WT_STRIDE + kk);
#pragma unroll
        for (int r = 0; r < 8; r++) {
            const ulonglong2 xv =
                *reinterpret_cast<const ulonglong2*>(xb + r * DIM + kk);  // broadcast
#pragma unroll
            for (int c = 0; c < 4; c++) {
                acc[r][c] = ffma2(xv.x, wv[c].x, acc[r][c]);
                acc[r][c] = ffma2(xv.y, wv[c].y, acc[r][c]);
            }
        }
    }

#pragma unroll
    for (int r = 0; r < 8; r++) {
        int row = row0 + rg * 8 + r;
        if (row < V) {
            float s  = g_dinv[row];
            float s2 = s * s;
            size_t base = (size_t)row * DIM + cg;
#pragma unroll
            for (int c = 0; c < 4; c++) {
                float v = hadd2(acc[r][c]);
                g_h[base + c * 32]     = v * s;   // coalesced per warp
                g_nodes[base + c * 32] = v * s2;
            }
        }
    }
}

// ---------------------------------------------------------------------------
// edge aggregation: one warp per edge; g_h already carries dinv[src].
// ---------------------------------------------------------------------------
__global__ void __launch_bounds__(256) k_edge_agg(const int* __restrict__ edge, int E) {
    int warp = (blockIdx.x * blockDim.x + threadIdx.x) >> 5;
    int lane = threadIdx.x & 31;
    if (warp >= E) return;
    int src = __ldg(edge + warp);       // edge_index[0]
    int dst = __ldg(edge + E + warp);   // edge_index[1]
    float norm = __ldg(g_dinv + dst);   // dinv[src] already folded into g_h
    const float4 v = reinterpret_cast<const float4*>(g_h)[(size_t)src * 32 + lane];
    float* p = g_nodes + (size_t)dst * DIM + lane * 4;
    asm volatile("red.global.add.v4.f32 [%0], {%1, %2, %3, %4};"
                 :: "l"(p), "f"(v.x * norm), "f"(v.y * norm),
                    "f"(v.z * norm), "f"(v.w * norm)
                 : "memory");
}

// ---------------------------------------------------------------------------
// scoring: shuffle-free. Block = 4 items x 64 samples; 1 thread = 1 sample.
// scores[b,s] = dot(nodes[item]+bias, nodes[sample]+bias)
// ---------------------------------------------------------------------------
__global__ void __launch_bounds__(256) k_scores(const int* __restrict__ items,
                                                const int* __restrict__ samples,
                                                const float* __restrict__ bias,
                                                float* __restrict__ out,
                                                int B, int S) {
    __shared__ float item_sh[4][DIM];   // item + bias
    __shared__ float bias_sh[DIM];
    const int t  = threadIdx.x;
    const int b0 = blockIdx.x * 4;

    if (t < DIM) bias_sh[t] = __ldg(bias + t);
    __syncthreads();
#pragma unroll
    for (int i = 0; i < 2; i++) {
        int lin = t + i * 256;          // 0..511
        int ii  = lin >> 7;             // item slot 0..3
        int d   = lin & 127;
        int bi  = b0 + ii;
        if (bi < B) {
            int item = __ldg(items + bi);
            item_sh[ii][d] = g_nodes[(size_t)item * DIM + d] + bias_sh[d];
        }
    }
    __syncthreads();

    const int ii = t >> 6;              // item slot
    const int s  = t & 63;              // sample index
    const int bi = b0 + ii;
    if (bi >= B) return;

    const int sidx = __ldg(samples + (size_t)bi * S + s);
    const float4* srow = reinterpret_cast<const float4*>(g_nodes) + (size_t)sidx * 32;
    const float4* irow = reinterpret_cast<const float4*>(item_sh[ii]);
    const float4* brow = reinterpret_cast<const float4*>(bias_sh);

    float4 acc = make_float4(0.f, 0.f, 0.f, 0.f);
#pragma unroll 8
    for (int j = 0; j < 32; j++) {
        float4 sv = srow[j];
        float4 iv = irow[j];
        float4 bv = brow[j];
        acc.x = fmaf(iv.x, sv.x + bv.x, acc.x);
        acc.y = fmaf(iv.y, sv.y + bv.y, acc.y);
        acc.z = fmaf(iv.z, sv.z + bv.z, acc.z);
        acc.w = fmaf(iv.w, sv.w + bv.w, acc.w);
    }
    out[(size_t)bi * S + s] = (acc.x + acc.y) + (acc.z + acc.w);
}

// ---------------------------------------------------------------------------
// launcher
// ---------------------------------------------------------------------------
extern "C" void kernel_launch(void* const* d_in, const int* in_sizes, int n_in,
                              void* d_out, int out_size) {
    const int*   items   = (const int*)d_in[0];
    const int*   samples = (const int*)d_in[1];
    const int*   edge    = (const int*)d_in[2];
    const float* emb     = (const float*)d_in[3];
    const float* W       = (const float*)d_in[4];
    const float* bias    = (const float*)d_in[5];
    float*       out     = (float*)d_out;

    const int B = in_sizes[0];
    const int S = in_sizes[1] / B;
    const int E = in_sizes[2] / 2;
    const int V = in_sizes[3] / DIM;

    // degrees
    k_init_deg<<<(V + 255) / 256, 256>>>(V);
    k_deg<<<(E + 255) / 256, 256>>>(edge, E);
    k_dinv<<<(V + 255) / 256, 256>>>(V);

    // W transpose (tiny)
    k_transpose_w<<<(DIM * DIM + 255) / 256, 256>>>(W);

    // GEMM + fused self-loop/scaling
    const int gemm_smem = (DIM * WT_STRIDE + 32 * DIM) * (int)sizeof(float); // 83968
    cudaFuncSetAttribute(k_gemm, cudaFuncAttributeMaxDynamicSharedMemorySize, gemm_smem);
    k_gemm<<<(V + 31) / 32, 128, gemm_smem>>>(emb, V);

    // edge scatter-add
    k_edge_agg<<<(E + 7) / 8, 256>>>(edge, E);

    // scoring with folded bias
    k_scores<<<(B + 3) / 4, 256>>>(items, samples, bias, out, B, S);
}

// round 4
// speedup vs baseline: 1.9194x; 1.3869x over previous
#include <cuda_runtime.h>
#include <cuda_bf16.h>
#include <cstdint>

#define DIM 128
#define WT_STRIDE 132   // padded row stride for transposed W
#define MAXV 100000

// Scratch (device globals; no allocation allowed)
__device__ float g_h[MAXV * DIM];      // dinv[v] * (emb @ W)[v]
__device__ float g_nodes[MAXV * DIM];  // aggregated output (pre-bias)
__device__ float g_deg[MAXV];
__device__ float g_dinv[MAXV];
__device__ float g_wt[DIM * WT_STRIDE]; // g_wt[c*132 + k] = W[k][c]

// ---------------------------------------------------------------------------
// packed f32x2 helpers
// ---------------------------------------------------------------------------
__device__ __forceinline__ unsigned long long ffma2(unsigned long long a,
                                                    unsigned long long b,
                                                    unsigned long long c) {
    unsigned long long d;
    asm("fma.rn.f32x2 %0, %1, %2, %3;" : "=l"(d) : "l"(a), "l"(b), "l"(c));
    return d;
}
__device__ __forceinline__ float hadd2(unsigned long long p) {
    float lo, hi;
    asm("mov.b64 {%0, %1}, %2;" : "=f"(lo), "=f"(hi) : "l"(p));
    return lo + hi;
}

// ---------------------------------------------------------------------------
// prep: deg=1 (self-loop) + transpose W into padded g_wt (fused)
// ---------------------------------------------------------------------------
__global__ void k_prep(const float* __restrict__ W, int V) {
    int gid = blockIdx.x * blockDim.x + threadIdx.x;
    if (gid < V) g_deg[gid] = 1.0f;
    if (gid < DIM * DIM) {
        int k = gid >> 7;
        int c = gid & 127;
        g_wt[c * WT_STRIDE + k] = W[gid];
    }
}

__global__ void k_deg(const int* __restrict__ edge, int E) {
    int e = blockIdx.x * blockDim.x + threadIdx.x;
    if (e < E) atomicAdd(&g_deg[edge[E + e]], 1.0f);  // dst = edge_index[1]
}

__global__ void k_dinv(int V) {
    int v = blockIdx.x * blockDim.x + threadIdx.x;
    if (v < V) g_dinv[v] = rsqrtf(g_deg[v]);
}

// ---------------------------------------------------------------------------
// GEMM: g_h = dinv * (X @ W), g_nodes = dinv^2 * (X @ W)   (selfloop fused)
// k-packed f32x2. Block = 256 threads = 8 warps; block tile 64 rows x 128 cols.
// Thread tile: 8 rows (rg*8..+7, warp-uniform -> broadcast LDS) x 4 cols
// (cg + c*32; lane stride 132 words == 4 mod 32 -> conflict-free LDS.128).
// smem 98KB -> 2 blocks/SM (16 warps/SM).
// ---------------------------------------------------------------------------
__global__ void __launch_bounds__(256) k_gemm(const float* __restrict__ X, int V) {
    extern __shared__ float sh[];
    float* w_sh = sh;                         // [128][132]
    float* x_sh = sh + DIM * WT_STRIDE;       // [64][128]

    const int tid  = threadIdx.x;
    const int row0 = blockIdx.x * 64;

    // load transposed W: 4224 float4; 17 per thread (guarded)
    {
        const float4* src = reinterpret_cast<const float4*>(g_wt);
        float4* dst = reinterpret_cast<float4*>(w_sh);
        const int total = DIM * (WT_STRIDE / 4);  // 4224
#pragma unroll
        for (int i = 0; i < 17; i++) {
            int idx = tid + i * 256;
            if (idx < total) dst[idx] = src[idx];
        }
    }
    // load X tile: 64 rows x 32 float4 = 2048; 8 per thread (row-guarded)
    {
        const float4* X4 = reinterpret_cast<const float4*>(X) + (size_t)row0 * 32;
        float4* x4 = reinterpret_cast<float4*>(x_sh);
#pragma unroll
        for (int i = 0; i < 8; i++) {
            int idx = tid + i * 256;
            int r = idx >> 5;
            float4 v = make_float4(0.f, 0.f, 0.f, 0.f);
            if (row0 + r < V) v = X4[idx];
            x4[idx] = v;
        }
    }
    __syncthreads();

    const int cg = tid & 31;   // cols: cg, cg+32, cg+64, cg+96
    const int rg = tid >> 5;   // rows: rg*8 .. rg*8+7  (8 row-groups)

    unsigned long long acc[8][4];
#pragma unroll
    for (int r = 0; r < 8; r++)
#pragma unroll
        for (int c = 0; c < 4; c++) acc[r][c] = 0ull;

    const float* xb = x_sh + (rg * 8) * DIM;
    const float* wb = w_sh + cg * WT_STRIDE;

#pragma unroll 4
    for (int kk = 0; kk < DIM; kk += 4) {
        ulonglong2 wv[4];
#pragma unroll
        for (int c = 0; c < 4; c++)
            wv[c] = *reinterpret_cast<const ulonglong2*>(wb + (c * 32) * WT_STRIDE + kk);
#pragma unroll
        for (int r = 0; r < 8; r++) {
            const ulonglong2 xv =
                *reinterpret_cast<const ulonglong2*>(xb + r * DIM + kk);  // broadcast
#pragma unroll
            for (int c = 0; c < 4; c++) {
                acc[r][c] = ffma2(xv.x, wv[c].x, acc[r][c]);
                acc[r][c] = ffma2(xv.y, wv[c].y, acc[r][c]);
            }
        }
    }

#pragma unroll
    for (int r = 0; r < 8; r++) {
        int row = row0 + rg * 8 + r;
        if (row < V) {
            float s  = g_dinv[row];
            float s2 = s * s;
            size_t base = (size_t)row * DIM + cg;
#pragma unroll
            for (int c = 0; c < 4; c++) {
                float v = hadd2(acc[r][c]);
                g_h[base + c * 32]     = v * s;   // coalesced per warp
                g_nodes[base + c * 32] = v * s2;
            }
        }
    }
}

// ---------------------------------------------------------------------------
// edge aggregation: one warp per edge; g_h already carries dinv[src].
// ---------------------------------------------------------------------------
__global__ void __launch_bounds__(256) k_edge_agg(const int* __restrict__ edge, int E) {
    int warp = (blockIdx.x * blockDim.x + threadIdx.x) >> 5;
    int lane = threadIdx.x & 31;
    if (warp >= E) return;
    int src = __ldg(edge + warp);       // edge_index[0]
    int dst = __ldg(edge + E + warp);   // edge_index[1]
    float norm = __ldg(g_dinv + dst);   // dinv[src] already folded into g_h
    const float4 v = reinterpret_cast<const float4*>(g_h)[(size_t)src * 32 + lane];
    float* p = g_nodes + (size_t)dst * DIM + lane * 4;
    asm volatile("red.global.add.v4.f32 [%0], {%1, %2, %3, %4};"
                 :: "l"(p), "f"(v.x * norm), "f"(v.y * norm),
                    "f"(v.z * norm), "f"(v.w * norm)
                 : "memory");
}

// ---------------------------------------------------------------------------
// scoring: block = one item; 4 warps x 16 samples; bias folded in.
// scores[b,s] = dot(nodes[item]+bias, nodes[sample]+bias)
// Warp-per-sample: each LDG.128 covers one contiguous 512B row (coalesced).
// ---------------------------------------------------------------------------
__global__ void __launch_bounds__(128) k_scores(const int* __restrict__ items,
                                                const int* __restrict__ samples,
                                                const float* __restrict__ bias,
                                                float* __restrict__ out, int S) {
    __shared__ float item_sh[DIM];
    __shared__ float bias_sh[DIM];
    const int b = blockIdx.x;
    const int t = threadIdx.x;

    const int item = __ldg(items + b);
    {
        float bv = __ldg(bias + t);
        bias_sh[t] = bv;
        item_sh[t] = g_nodes[(size_t)item * DIM + t] + bv;
    }
    __syncthreads();

    const int warp = t >> 5;
    const int lane = t & 31;
    const float4 iv = reinterpret_cast<const float4*>(item_sh)[lane];
    const float4 bv = reinterpret_cast<const float4*>(bias_sh)[lane];

    const int* samp = samples + (size_t)b * S;
#pragma unroll 4
    for (int i = 0; i < 16; i++) {
        int s = warp * 16 + i;
        int sidx = __ldg(samp + s);
        const float4 sv = reinterpret_cast<const float4*>(g_nodes)[(size_t)sidx * 32 + lane];
        float p = iv.x * (sv.x + bv.x) + iv.y * (sv.y + bv.y) +
                  iv.z * (sv.z + bv.z) + iv.w * (sv.w + bv.w);
#pragma unroll
        for (int off = 16; off > 0; off >>= 1)
            p += __shfl_xor_sync(0xffffffffu, p, off);
        if (lane == 0) out[(size_t)b * S + s] = p;
    }
}

// ---------------------------------------------------------------------------
// launcher
// ---------------------------------------------------------------------------
extern "C" void kernel_launch(void* const* d_in, const int* in_sizes, int n_in,
                              void* d_out, int out_size) {
    const int*   items   = (const int*)d_in[0];
    const int*   samples = (const int*)d_in[1];
    const int*   edge    = (const int*)d_in[2];
    const float* emb     = (const float*)d_in[3];
    const float* W       = (const float*)d_in[4];
    const float* bias    = (const float*)d_in[5];
    float*       out     = (float*)d_out;

    const int B = in_sizes[0];
    const int S = in_sizes[1] / B;
    const int E = in_sizes[2] / 2;
    const int V = in_sizes[3] / DIM;

    // prep (deg=1 + W transpose), degrees
    k_prep<<<(V + 255) / 256, 256>>>(W, V);
    k_deg<<<(E + 255) / 256, 256>>>(edge, E);
    k_dinv<<<(V + 255) / 256, 256>>>(V);

    // GEMM + fused self-loop/scaling (98KB dynamic smem)
    const int gemm_smem = (DIM * WT_STRIDE + 64 * DIM) * (int)sizeof(float); // 100352
    cudaFuncSetAttribute(k_gemm, cudaFuncAttributeMaxDynamicSharedMemorySize, gemm_smem);
    k_gemm<<<(V + 63) / 64, 256, gemm_smem>>>(emb, V);

    // edge scatter-add
    k_edge_agg<<<(E + 7) / 8, 256>>>(edge, E);

    // scoring with folded bias
    k_scores<<<B, 128>>>(items, samples, bias, out, S);
}